// round 2
// baseline (speedup 1.0000x reference)
#include <cuda_runtime.h>
#include <cuda_bf16.h>

// RoIAlign: features [B=4, C=1024, H=64, W=64] f32, rois [N=2048, 5] f32
// out [N, C, 7, 7] f32.
//
// Strategy: block = (batch b, 8-channel chunk). Stage the 8 feature planes in
// shared memory (row stride padded 64->65 so smem bank = (hs+ws)%32, near
// conflict-free scatter). A prekernel compacts roi indices per batch so each
// block only visits its own rois. Thread = (roi_slot, bin); roi geometry is
// computed once per bin in registers and amortized over the 8-channel inner
// loop (4 LDS + 4 FMA + 1 STG per output).

#define B_    4
#define C_    1024
#define H_    64
#define W_    64
#define N_    2048
#define AHW   7
#define BINS  49
#define SCALE 0.0625f

#define CH        8                  // channels per block
#define PLANE_W   65                 // padded row stride (floats)
#define PLANE     (H_ * PLANE_W)     // 4160 floats per plane
#define SMEM_FLT  (CH * PLANE)       // 33280 floats
#define SMEM_BYTES (SMEM_FLT * 4)    // 133120 B
#define NTHREADS  512
#define RPI       10                 // rois per chunk (10*49 = 490 <= 512)

__device__ int g_roi_list[B_][N_];
__device__ int g_roi_cnt[B_];

__global__ void zero_cnt_kernel() {
    if (threadIdx.x < B_) g_roi_cnt[threadIdx.x] = 0;
}

__global__ void build_list_kernel(const float* __restrict__ rois) {
    int n = blockIdx.x * blockDim.x + threadIdx.x;
    if (n < N_) {
        int b = (int)rois[n * 5];
        int pos = atomicAdd(&g_roi_cnt[b], 1);
        g_roi_list[b][pos] = n;
    }
}

__global__ __launch_bounds__(NTHREADS, 1)
void roialign_kernel(const float* __restrict__ features,
                     const float* __restrict__ rois,
                     float* __restrict__ out) {
    extern __shared__ float sm[];

    const int b  = blockIdx.y;
    const int c0 = blockIdx.x * CH;

    // ---- Stage CH planes (contiguous in gmem) into padded smem ----
    {
        const float4* src =
            (const float4*)(features + (size_t)(b * C_ + c0) * (H_ * W_));
        for (int i = threadIdx.x; i < CH * H_ * W_ / 4; i += NTHREADS) {
            float4 v = src[i];
            int f   = i * 4;
            int c   = f >> 12;        // /4096
            int rem = f & 4095;
            int row = rem >> 6;       // /64
            int col = rem & 63;
            float* d = sm + c * PLANE + row * PLANE_W + col;
            d[0] = v.x; d[1] = v.y; d[2] = v.z; d[3] = v.w;
        }
    }
    __syncthreads();

    const int cnt  = g_roi_cnt[b];
    const int rsub = threadIdx.x / BINS;      // 0..10
    const int bin  = threadIdx.x - rsub * BINS;
    const float phf = (float)(bin / AHW);
    const float pwf = (float)(bin % AHW);
    const bool lane_ok = threadIdx.x < RPI * BINS;

    for (int base = 0; base < cnt; base += RPI) {
        int r = base + rsub;
        if (lane_ok && r < cnt) {
            int n = g_roi_list[b][r];
            const float* rp = rois + n * 5;
            float x1 = __ldg(rp + 1) * SCALE;
            float y1 = __ldg(rp + 2) * SCALE;
            float x2 = __ldg(rp + 3) * SCALE;
            float y2 = __ldg(rp + 4) * SCALE;

            float bw = fmaxf(x2 - x1, 0.0f) * (1.0f / 6.0f);
            float bh = fmaxf(y2 - y1, 0.0f) * (1.0f / 6.0f);
            float h  = y1 + phf * bh;
            float w  = x1 + pwf * bw;

            // exact replication of reference math
            float hstart = fminf(floorf(h), (float)(H_ - 2));
            float wstart = fminf(floorf(w), (float)(W_ - 2));
            float hr = h - hstart;
            float wr = w - wstart;
            bool valid = (h >= 0.0f) && (h < (float)H_) &&
                         (w >= 0.0f) && (w < (float)W_);
            int hs = min(max((int)hstart, 0), H_ - 2);
            int ws = min(max((int)wstart, 0), W_ - 2);

            float wa = (1.0f - hr) * (1.0f - wr);
            float wb = (1.0f - hr) * wr;
            float wc = hr * (1.0f - wr);
            float wd = hr * wr;
            if (!valid) { wa = wb = wc = wd = 0.0f; }

            const float* sp = sm + hs * PLANE_W + ws;
            float* o = out + ((size_t)n * C_ + c0) * BINS + bin;

            #pragma unroll
            for (int c = 0; c < CH; c++) {
                float ul = sp[0];
                float ur = sp[1];
                float dl = sp[PLANE_W];
                float dr = sp[PLANE_W + 1];
                o[0] = wa * ul + wb * ur + wc * dl + wd * dr;
                sp += PLANE;
                o  += BINS;
            }
        }
    }
}

extern "C" void kernel_launch(void* const* d_in, const int* in_sizes, int n_in,
                              void* d_out, int out_size) {
    const float* features = (const float*)d_in[0];
    const float* rois     = (const float*)d_in[1];
    float* out            = (float*)d_out;

    cudaFuncSetAttribute(roialign_kernel,
                         cudaFuncAttributeMaxDynamicSharedMemorySize,
                         SMEM_BYTES);

    zero_cnt_kernel<<<1, 32>>>();
    build_list_kernel<<<N_ / 256, 256>>>(rois);

    dim3 grid(C_ / CH, B_);
    roialign_kernel<<<grid, NTHREADS, SMEM_BYTES>>>(features, rois, out);
}